// round 7
// baseline (speedup 1.0000x reference)
#include <cuda_runtime.h>
#include <cuda_fp16.h>
#include <cuda_fp8.h>
#include <math.h>
#include <stdint.h>

#define N_NODES 50000
#define N_EDGES 800000
#define N_PAIRS 100000
#define IN_CH 128
#define HID 256
#define EMB 32
#define CAT_EMB 8
#define MAX_TOK 20
#define F0 160   // IN_CH + EMB
#define F1 256   // HID

// ---------------- scratch ----------------
__device__ __half g_h0h[N_NODES * F0];                 // fp16 (GEMM self-term)
__device__ unsigned char g_h0q[N_NODES * F0];          // fp8 e4m3 (gather path)
__device__ __half g_aggh[N_NODES * F1];                // fp16 agg (GEMM A)
__device__ __half g_h1h[N_NODES * F1];
__device__ unsigned char g_h1q[N_NODES * F1];          // fp8 e4m3 (gather path)
__device__ __half g_zh[N_NODES * F1];
__device__ int    g_cnt[N_NODES];
__device__ int    g_off[N_NODES + 1];
__device__ int    g_cur[N_NODES];
__device__ int    g_csr[N_EDGES];
__device__ float  g_invdeg[N_NODES];

// pre-transposed fp16 weights: slot = layer*2 + (0:W_l, 1:W_r); layout [n][k]
__device__ __half g_wt[4][256 * 256];

#define SCAN_BLK 256
#define SCAN_GRID ((N_NODES + SCAN_BLK - 1) / SCAN_BLK)
__device__ int g_bsum[SCAN_GRID];

// ================= mma.sync helpers =================
__device__ __forceinline__ uint32_t smem_u32(const void* p) {
    uint32_t a;
    asm("{ .reg .u64 t; cvta.to.shared.u64 t, %1; cvt.u32.u64 %0, t; }" : "=r"(a) : "l"(p));
    return a;
}
__device__ __forceinline__ void ldmx4(uint32_t* r, uint32_t addr) {
    asm volatile("ldmatrix.sync.aligned.m8n8.x4.shared.b16 {%0,%1,%2,%3}, [%4];"
                 : "=r"(r[0]), "=r"(r[1]), "=r"(r[2]), "=r"(r[3]) : "r"(addr));
}
__device__ __forceinline__ void hmma(float* c, const uint32_t* a, const uint32_t* b) {
    asm volatile("mma.sync.aligned.m16n8k16.row.col.f32.f16.f16.f32 "
                 "{%0,%1,%2,%3}, {%4,%5,%6,%7}, {%8,%9}, {%0,%1,%2,%3};"
                 : "+f"(c[0]), "+f"(c[1]), "+f"(c[2]), "+f"(c[3])
                 : "r"(a[0]), "r"(a[1]), "r"(a[2]), "r"(a[3]), "r"(b[0]), "r"(b[1]));
}

// smem stage layout (fp16, row stride 40 elems = 80B -> conflict-free ldmatrix)
#define ASTR2 80
#define A_H  0
#define B_H  10240
#define STAGE_BYTES 20480
#define SMEM_GEMM_TOTAL (2 * STAGE_BYTES)   // 40 KB

// ---------------- GWAS encoder + concat into h0 (fp16); also zeroes g_cnt ----------------
__global__ void gwas_kernel(const float* __restrict__ x,
                            const int* __restrict__ tok,
                            const float* __restrict__ scores,
                            const int* __restrict__ cat,
                            const float* __restrict__ trait_embed,
                            const float* __restrict__ cat_embed,
                            const float* __restrict__ proj_W,
                            const float* __restrict__ proj_b) {
    int gt = blockIdx.x * blockDim.x + threadIdx.x;
    if (gt < N_NODES) g_cnt[gt] = 0;

    int warp_in_block = threadIdx.x >> 5;
    int lane = threadIdx.x & 31;
    int n = blockIdx.x * (blockDim.x >> 5) + warp_in_block;
    if (n >= N_NODES) return;

    __shared__ float sh_acc[8][41];
    float acc_trait = 0.f, acc_cat = 0.f, acc_s = 0.f, wsum = 0.f;

    const int*   tk = tok    + (long long)n * MAX_TOK;
    const float* sc = scores + (long long)n * MAX_TOK;
    const int*   ct = cat    + (long long)n * MAX_TOK;

    for (int t = 0; t < MAX_TOK; ++t) {
        int   tid = tk[t];
        float s   = sc[t];
        int   cid = ct[t];
        float w   = (tid != 0) ? s : 0.f;
        wsum += w;
        acc_trait += w * trait_embed[tid * EMB + lane];
        if (lane < CAT_EMB) acc_cat += w * cat_embed[cid * CAT_EMB + lane];
        acc_s += w * s;
    }
    sh_acc[warp_in_block][lane] = acc_trait;
    if (lane < CAT_EMB) sh_acc[warp_in_block][EMB + lane] = acc_cat;
    if (lane == 0)      sh_acc[warp_in_block][EMB + CAT_EMB] = acc_s;
    __syncwarp();

    float inv = 1.f / fmaxf(wsum, 1e-8f);
    float o = wsum * proj_b[lane];
    const float* shv = sh_acc[warp_in_block];
#pragma unroll
    for (int k = 0; k < 41; ++k)
        o += shv[k] * proj_W[k * EMB + lane];

    __half* hrow = g_h0h + (long long)n * F0;
    hrow[IN_CH + lane] = __float2half_rn(o * inv);
    const float* xrow = x + (long long)n * IN_CH;
#pragma unroll
    for (int i = 0; i < 4; ++i)
        hrow[lane + i * 32] = __float2half_rn(xrow[lane + i * 32]);
}

// ---------------- h0 fp16 -> fp8 repack (gather copy) ----------------
__global__ void quant_h0_kernel() {
    int i = blockIdx.x * blockDim.x + threadIdx.x;
    if (i >= N_NODES * F0 / 8) return;
    uint4 v = ((const uint4*)g_h0h)[i];
    const __half2* h = (const __half2*)&v;
    uint2 o;
    unsigned short* s = (unsigned short*)&o;
#pragma unroll
    for (int k = 0; k < 4; ++k) {
        __half2_raw hr = *(const __half2_raw*)&h[k];
        s[k] = __nv_cvt_halfraw2_to_fp8x2(hr, __NV_SATFINITE, __NV_E4M3);
    }
    ((uint2*)g_h0q)[i] = o;
}

// ---------------- weight transpose -> fp16 (all 4 slots) ----------------
__global__ void wsplit_all_kernel(const float* __restrict__ Wl0, const float* __restrict__ Wr0,
                                  const float* __restrict__ Wl1, const float* __restrict__ Wr1) {
    int idx = blockIdx.x * blockDim.x + threadIdx.x;
    if (idx >= 256 * 256) return;
    int n = idx & 255, j = idx >> 8;
    const float* Ws[4] = {Wl0, Wr0, Wl1, Wr1};
    const int    Ks[4] = {F0, F0, F1, F1};
#pragma unroll
    for (int slot = 0; slot < 4; ++slot) {
        int K = Ks[slot];
        if (j < K)
            g_wt[slot][n * K + j] = __float2half_rn(Ws[slot][j * 256 + n]);
    }
}

// ---------------- CSR build ----------------
__global__ void count_kernel(const int* __restrict__ e_dst) {
    int e = blockIdx.x * blockDim.x + threadIdx.x;
    if (e < N_EDGES) atomicAdd(&g_cnt[e_dst[e]], 1);
}
__global__ void scan1_kernel() {
    __shared__ int sh[SCAN_BLK];
    int tid = threadIdx.x;
    int i = blockIdx.x * SCAN_BLK + tid;
    int v = (i < N_NODES) ? g_cnt[i] : 0;
    sh[tid] = v;
    __syncthreads();
#pragma unroll
    for (int off = 1; off < SCAN_BLK; off <<= 1) {
        int t = (tid >= off) ? sh[tid - off] : 0;
        __syncthreads();
        sh[tid] += t;
        __syncthreads();
    }
    if (i < N_NODES) g_off[i] = sh[tid] - v;
    if (tid == SCAN_BLK - 1) g_bsum[blockIdx.x] = sh[tid];
}
__global__ void scan2_kernel() {
    __shared__ int sh[SCAN_BLK];
    int tid = threadIdx.x;
    int v = (tid < SCAN_GRID) ? g_bsum[tid] : 0;
    sh[tid] = v;
    __syncthreads();
#pragma unroll
    for (int off = 1; off < SCAN_BLK; off <<= 1) {
        int t = (tid >= off) ? sh[tid - off] : 0;
        __syncthreads();
        sh[tid] += t;
        __syncthreads();
    }
    if (tid < SCAN_GRID) g_bsum[tid] = sh[tid] - v;
    if (tid == 0) g_off[N_NODES] = N_EDGES;
}
__global__ void scan3_kernel() {
    int tid = threadIdx.x;
    int i = blockIdx.x * SCAN_BLK + tid;
    if (i < N_NODES) {
        int o = g_off[i] + g_bsum[blockIdx.x];
        g_off[i] = o;
        g_cur[i] = o;
        g_invdeg[i] = 1.0f / fmaxf((float)g_cnt[i], 1.0f);
    }
}
__global__ void fill_kernel(const int* __restrict__ e_src, const int* __restrict__ e_dst) {
    int e = blockIdx.x * blockDim.x + threadIdx.x;
    if (e < N_EDGES) {
        int d = e_dst[e];
        int pos = atomicAdd(&g_cur[d], 1);
        g_csr[pos] = e_src[e];
    }
}

// ---------------- mean aggregation: fp8 gather, fp32 accum, fp16 store ----------------
// thread handles 16 channels (one uint4 = 16 fp8); blockDim.x = F/16
__global__ void aggregate_kernel(int layer) {
    const uint4* feat = (const uint4*)(layer ? g_h1q : g_h0q);
    int Fv16 = (layer ? F1 : F0) >> 4;
    int n = blockIdx.x * blockDim.y + threadIdx.y;
    if (n >= N_NODES) return;
    int c = threadIdx.x;
    int s = g_off[n], e = g_off[n + 1];
    float acc[16];
#pragma unroll
    for (int i = 0; i < 16; ++i) acc[i] = 0.f;
    for (int j = s; j < e; ++j) {
        int srcn = g_csr[j];
        uint4 v = feat[(size_t)srcn * Fv16 + c];
        const unsigned short* q = (const unsigned short*)&v;
#pragma unroll
        for (int i = 0; i < 8; ++i) {
            __half2_raw hr = __nv_cvt_fp8x2_to_halfraw2(q[i], __NV_E4M3);
            float2 f = __half22float2(*(__half2*)&hr);
            acc[2 * i]     += f.x;
            acc[2 * i + 1] += f.y;
        }
    }
    float sc = g_invdeg[n];
    uint4 outv[2];
    __half2* ho = (__half2*)outv;
#pragma unroll
    for (int i = 0; i < 8; ++i)
        ho[i] = __floats2half2_rn(acc[2 * i] * sc, acc[2 * i + 1] * sc);
    uint4* dst = (uint4*)g_aggh + (size_t)n * (Fv16 * 2) + c * 2;
    dst[0] = outv[0];
    dst[1] = outv[1];
}

// ---------------- tensor-core GEMM: C = relu(agg@Wl + x@Wr + b), fp16 ----------------
struct Pref {
    uint4 a[2], b[2];
};

__device__ __forceinline__ void ldg_chunk(Pref& p, int layer, int F, int nc,
                                          int t, int row0, int col0) {
    int hf = (t >= nc) ? 1 : 0;
    int k0 = (t - hf * nc) * 32;
    const __half* Asrc = hf ? (layer ? g_h1h : g_h0h) : g_aggh;
    const __half* Bsrc = g_wt[layer * 2 + hf];
    int tid = threadIdx.x;
#pragma unroll
    for (int j = 0; j < 2; ++j) {
        int i = tid + j * 256;
        int r = i >> 2, q8 = (i & 3) * 8;
        int gm = row0 + r;
        p.a[j] = (gm < N_NODES) ? *(const uint4*)(Asrc + (size_t)gm * F + k0 + q8)
                                : make_uint4(0, 0, 0, 0);
        p.b[j] = *(const uint4*)(Bsrc + (size_t)(col0 + r) * F + k0 + q8);
    }
}

__device__ __forceinline__ void sts_chunk(const Pref& p, char* stage) {
    int tid = threadIdx.x;
#pragma unroll
    for (int j = 0; j < 2; ++j) {
        int i = tid + j * 256;
        int r = i >> 2, b16 = (i & 3) * 16;
        *(uint4*)(stage + A_H + r * ASTR2 + b16) = p.a[j];
        *(uint4*)(stage + B_H + r * ASTR2 + b16) = p.b[j];
    }
}

__global__ __launch_bounds__(256)
void gemm_mma_kernel(const float* __restrict__ bias, int layer) {
    extern __shared__ char smem[];
    const int F  = layer ? F1 : F0;
    const int nc = F / 32;
    const int T  = 2 * nc;
    const int row0 = blockIdx.x * 128;
    const int col0 = blockIdx.y * 128;
    __half* C = layer ? g_zh : g_h1h;

    const int tid = threadIdx.x, wid = tid >> 5, lane = tid & 31;
    const int wm0 = (wid >> 2) * 64;
    const int wn0 = (wid & 3) * 32;

    float acc[4][4][4];
#pragma unroll
    for (int a = 0; a < 4; ++a)
#pragma unroll
        for (int b = 0; b < 4; ++b)
#pragma unroll
            for (int c = 0; c < 4; ++c) acc[a][b][c] = 0.f;

    Pref p;
    ldg_chunk(p, layer, F, nc, 0, row0, col0);
    sts_chunk(p, smem);
    __syncthreads();

    const uint32_t sbase = smem_u32(smem);
    const int b_row = ((lane >> 4) & 1) * 8 + (lane & 7);
    const int b_khalf = ((lane >> 3) & 1) * 8;
    const int a_row = lane & 15;
    const int a_khalf = ((lane >> 4) & 1) * 8;

    for (int t = 0; t < T; ++t) {
        if (t + 1 < T) ldg_chunk(p, layer, F, nc, t + 1, row0, col0);
        const uint32_t sb = sbase + (uint32_t)(t & 1) * STAGE_BYTES;
#pragma unroll
        for (int ks = 0; ks < 2; ++ks) {
            uint32_t bh[4][2];
            {
                uint32_t r[4];
                uint32_t ad = sb + B_H + (uint32_t)((wn0 + b_row) * ASTR2 + (ks * 16 + b_khalf) * 2);
                ldmx4(r, ad);
                bh[0][0] = r[0]; bh[0][1] = r[1]; bh[1][0] = r[2]; bh[1][1] = r[3];
                ldmx4(r, ad + 16 * ASTR2);
                bh[2][0] = r[0]; bh[2][1] = r[1]; bh[3][0] = r[2]; bh[3][1] = r[3];
            }
            uint32_t ah[4][4];
#pragma unroll
            for (int mt = 0; mt < 4; ++mt) {
                uint32_t roff = (uint32_t)((wm0 + mt * 16 + a_row) * ASTR2 + (ks * 16 + a_khalf) * 2);
                ldmx4(ah[mt], sb + A_H + roff);
            }
#pragma unroll
            for (int mt = 0; mt < 4; ++mt)
#pragma unroll
                for (int nt = 0; nt < 4; ++nt)
                    hmma(acc[mt][nt], ah[mt], bh[nt]);
        }
        if (t + 1 < T) sts_chunk(p, smem + ((t + 1) & 1) * STAGE_BYTES);
        __syncthreads();
    }

    // epilogue: bias + relu + fp16 store (+ fp8 gather copy for layer 0)
#pragma unroll
    for (int mt = 0; mt < 4; ++mt) {
        int rbase = row0 + wm0 + mt * 16 + (lane >> 2);
#pragma unroll
        for (int hh = 0; hh < 2; ++hh) {
            int gm = rbase + hh * 8;
            if (gm < N_NODES) {
                __half* crow = C + (size_t)gm * HID;
                unsigned char* qrow = g_h1q + (size_t)gm * HID;
#pragma unroll
                for (int nt = 0; nt < 4; ++nt) {
                    int cn = col0 + wn0 + nt * 8 + (lane & 3) * 2;
                    float v0 = fmaxf(acc[mt][nt][hh * 2]     + bias[cn], 0.f);
                    float v1 = fmaxf(acc[mt][nt][hh * 2 + 1] + bias[cn + 1], 0.f);
                    *(__half2*)(crow + cn) = __floats2half2_rn(v0, v1);
                    if (layer == 0) {
                        *(unsigned short*)(qrow + cn) =
                            __nv_cvt_float2_to_fp8x2(make_float2(v0, v1),
                                                     __NV_SATFINITE, __NV_E4M3);
                    }
                }
            }
        }
    }
}

// ---------------- pair scoring: sigmoid(dot(z[src], z[dst])), fp16 gather ----------------
__global__ void pair_kernel(const int* __restrict__ src,
                            const int* __restrict__ dst,
                            float* __restrict__ out) {
    int gw = (blockIdx.x * blockDim.x + threadIdx.x) >> 5;
    int lane = threadIdx.x & 31;
    if (gw >= N_PAIRS) return;
    int a = src[gw], b = dst[gw];
    uint4 va = ((const uint4*)(g_zh + (size_t)a * HID))[lane];
    uint4 vb = ((const uint4*)(g_zh + (size_t)b * HID))[lane];
    const __half2* ha = (const __half2*)&va;
    const __half2* hb = (const __half2*)&vb;
    float acc = 0.f;
#pragma unroll
    for (int i = 0; i < 4; ++i) {
        float2 fa = __half22float2(ha[i]);
        float2 fb = __half22float2(hb[i]);
        acc += fa.x * fb.x + fa.y * fb.y;
    }
#pragma unroll
    for (int o = 16; o; o >>= 1) acc += __shfl_xor_sync(0xFFFFFFFFu, acc, o);
    if (lane == 0) out[gw] = 1.f / (1.f + expf(-acc));
}

// ---------------- launch ----------------
extern "C" void kernel_launch(void* const* d_in, const int* in_sizes, int n_in,
                              void* d_out, int out_size) {
    const float* x           = (const float*)d_in[0];
    const int*   tok_ids     = (const int*)  d_in[1];
    const float* scores      = (const float*)d_in[2];
    const int*   cat_ids     = (const int*)  d_in[3];
    const int*   edge_index  = (const int*)  d_in[4];
    const int*   src         = (const int*)  d_in[5];
    const int*   dst         = (const int*)  d_in[6];
    const float* trait_embed = (const float*)d_in[7];
    const float* cat_embed   = (const float*)d_in[8];
    const float* proj_W      = (const float*)d_in[9];
    const float* proj_b      = (const float*)d_in[10];
    const float* W_l0        = (const float*)d_in[11];
    const float* b_l0        = (const float*)d_in[12];
    const float* W_r0        = (const float*)d_in[13];
    const float* W_l1        = (const float*)d_in[14];
    const float* b_l1        = (const float*)d_in[15];
    const float* W_r1        = (const float*)d_in[16];
    float* out = (float*)d_out;

    const int* e_src = edge_index;
    const int* e_dst = edge_index + N_EDGES;

    cudaFuncSetAttribute(gemm_mma_kernel,
                         cudaFuncAttributeMaxDynamicSharedMemorySize, SMEM_GEMM_TOTAL);

    gwas_kernel<<<(N_NODES + 7) / 8, 256>>>(x, tok_ids, scores, cat_ids,
                                            trait_embed, cat_embed, proj_W, proj_b);
    quant_h0_kernel<<<(N_NODES * F0 / 8 + 255) / 256, 256>>>();

    wsplit_all_kernel<<<(256 * 256 + 255) / 256, 256>>>(W_l0, W_r0, W_l1, W_r1);

    count_kernel<<<(N_EDGES + 255) / 256, 256>>>(e_dst);
    scan1_kernel<<<SCAN_GRID, SCAN_BLK>>>();
    scan2_kernel<<<1, SCAN_BLK>>>();
    scan3_kernel<<<SCAN_GRID, SCAN_BLK>>>();
    fill_kernel<<<(N_EDGES + 255) / 256, 256>>>(e_src, e_dst);

    const dim3 ggrid((N_NODES + 127) / 128, 2);

    // Layer 0
    {
        dim3 blk(F0 / 16, 24);   // 10 x 24 = 240
        aggregate_kernel<<<(N_NODES + 23) / 24, blk>>>(0);
        gemm_mma_kernel<<<ggrid, 256, SMEM_GEMM_TOTAL>>>(b_l0, 0);
    }
    // Layer 1
    {
        dim3 blk(F1 / 16, 16);   // 16 x 16 = 256
        aggregate_kernel<<<(N_NODES + 15) / 16, blk>>>(1);
        gemm_mma_kernel<<<ggrid, 256, SMEM_GEMM_TOTAL>>>(b_l1, 1);
    }

    pair_kernel<<<(N_PAIRS * 32 + 255) / 256, 256>>>(src, dst, out);
}

// round 8
// speedup vs baseline: 1.1350x; 1.1350x over previous
#include <cuda_runtime.h>
#include <cuda_fp16.h>
#include <math.h>
#include <stdint.h>

#define N_NODES 50000
#define N_EDGES 800000
#define N_PAIRS 100000
#define IN_CH 128
#define HID 256
#define EMB 32
#define CAT_EMB 8
#define MAX_TOK 20
#define F0 160   // IN_CH + EMB
#define F1 256   // HID

// ---------------- scratch (fp16 feature tables, fp32 accumulation) ----------------
__device__ __half g_h0h[N_NODES * F0];
__device__ __half g_aggh[N_NODES * F1];
__device__ __half g_h1h[N_NODES * F1];
__device__ __half g_zh[N_NODES * F1];
__device__ int    g_cnt[N_NODES];
__device__ int    g_off[N_NODES + 1];
__device__ int    g_cur[N_NODES];
__device__ int    g_csr[N_EDGES];
__device__ float  g_invdeg[N_NODES];

// pre-transposed fp16 weights: slot = layer*2 + (0:W_l, 1:W_r); layout [n][k]
__device__ __half g_wt[4][256 * 256];

#define SCAN_BLK 256
#define SCAN_GRID ((N_NODES + SCAN_BLK - 1) / SCAN_BLK)
__device__ int g_bsum[SCAN_GRID];

// ================= mma.sync helpers =================
__device__ __forceinline__ uint32_t smem_u32(const void* p) {
    uint32_t a;
    asm("{ .reg .u64 t; cvta.to.shared.u64 t, %1; cvt.u32.u64 %0, t; }" : "=r"(a) : "l"(p));
    return a;
}
__device__ __forceinline__ void ldmx4(uint32_t* r, uint32_t addr) {
    asm volatile("ldmatrix.sync.aligned.m8n8.x4.shared.b16 {%0,%1,%2,%3}, [%4];"
                 : "=r"(r[0]), "=r"(r[1]), "=r"(r[2]), "=r"(r[3]) : "r"(addr));
}
__device__ __forceinline__ void hmma(float* c, const uint32_t* a, const uint32_t* b) {
    asm volatile("mma.sync.aligned.m16n8k16.row.col.f32.f16.f16.f32 "
                 "{%0,%1,%2,%3}, {%4,%5,%6,%7}, {%8,%9}, {%0,%1,%2,%3};"
                 : "+f"(c[0]), "+f"(c[1]), "+f"(c[2]), "+f"(c[3])
                 : "r"(a[0]), "r"(a[1]), "r"(a[2]), "r"(a[3]), "r"(b[0]), "r"(b[1]));
}

// smem stage layout (fp16, row stride 40 elems = 80B -> conflict-free ldmatrix)
#define ASTR2 80
#define A_H  0
#define B_H  10240
#define STAGE_BYTES 20480
#define SMEM_GEMM_TOTAL (2 * STAGE_BYTES)   // 40 KB

// ---------------- GWAS encoder + concat into h0 (fp16) ----------------
__global__ void gwas_kernel(const float* __restrict__ x,
                            const int* __restrict__ tok,
                            const float* __restrict__ scores,
                            const int* __restrict__ cat,
                            const float* __restrict__ trait_embed,
                            const float* __restrict__ cat_embed,
                            const float* __restrict__ proj_W,
                            const float* __restrict__ proj_b) {
    int warp_in_block = threadIdx.x >> 5;
    int lane = threadIdx.x & 31;
    int n = blockIdx.x * (blockDim.x >> 5) + warp_in_block;
    if (n >= N_NODES) return;

    __shared__ float sh_acc[8][41];
    float acc_trait = 0.f, acc_cat = 0.f, acc_s = 0.f, wsum = 0.f;

    const int*   tk = tok    + (long long)n * MAX_TOK;
    const float* sc = scores + (long long)n * MAX_TOK;
    const int*   ct = cat    + (long long)n * MAX_TOK;

    for (int t = 0; t < MAX_TOK; ++t) {
        int   tid = tk[t];
        float s   = sc[t];
        int   cid = ct[t];
        float w   = (tid != 0) ? s : 0.f;
        wsum += w;
        acc_trait += w * trait_embed[tid * EMB + lane];
        if (lane < CAT_EMB) acc_cat += w * cat_embed[cid * CAT_EMB + lane];
        acc_s += w * s;
    }
    sh_acc[warp_in_block][lane] = acc_trait;
    if (lane < CAT_EMB) sh_acc[warp_in_block][EMB + lane] = acc_cat;
    if (lane == 0)      sh_acc[warp_in_block][EMB + CAT_EMB] = acc_s;
    __syncwarp();

    float inv = 1.f / fmaxf(wsum, 1e-8f);
    float o = wsum * proj_b[lane];
    const float* shv = sh_acc[warp_in_block];
#pragma unroll
    for (int k = 0; k < 41; ++k)
        o += shv[k] * proj_W[k * EMB + lane];

    __half* hrow = g_h0h + (long long)n * F0;
    hrow[IN_CH + lane] = __float2half_rn(o * inv);
    const float* xrow = x + (long long)n * IN_CH;
#pragma unroll
    for (int i = 0; i < 4; ++i)
        hrow[lane + i * 32] = __float2half_rn(xrow[lane + i * 32]);
}

// ---------------- weight transpose -> fp16 (all 4 slots) ----------------
__global__ void wsplit_all_kernel(const float* __restrict__ Wl0, const float* __restrict__ Wr0,
                                  const float* __restrict__ Wl1, const float* __restrict__ Wr1) {
    int idx = blockIdx.x * blockDim.x + threadIdx.x;
    if (idx >= 256 * 256) return;
    int n = idx & 255, j = idx >> 8;
    const float* Ws[4] = {Wl0, Wr0, Wl1, Wr1};
    const int    Ks[4] = {F0, F0, F1, F1};
#pragma unroll
    for (int slot = 0; slot < 4; ++slot) {
        int K = Ks[slot];
        if (j < K)
            g_wt[slot][n * K + j] = __float2half_rn(Ws[slot][j * 256 + n]);
    }
}

// ---------------- CSR build ----------------
__global__ void zero_cnt_kernel() {
    int i = blockIdx.x * blockDim.x + threadIdx.x;
    if (i < N_NODES) g_cnt[i] = 0;
}
__global__ void count_kernel(const int* __restrict__ e_dst) {
    int e = blockIdx.x * blockDim.x + threadIdx.x;
    if (e < N_EDGES) atomicAdd(&g_cnt[e_dst[e]], 1);
}
__global__ void scan1_kernel() {
    __shared__ int sh[SCAN_BLK];
    int tid = threadIdx.x;
    int i = blockIdx.x * SCAN_BLK + tid;
    int v = (i < N_NODES) ? g_cnt[i] : 0;
    sh[tid] = v;
    __syncthreads();
#pragma unroll
    for (int off = 1; off < SCAN_BLK; off <<= 1) {
        int t = (tid >= off) ? sh[tid - off] : 0;
        __syncthreads();
        sh[tid] += t;
        __syncthreads();
    }
    if (i < N_NODES) g_off[i] = sh[tid] - v;
    if (tid == SCAN_BLK - 1) g_bsum[blockIdx.x] = sh[tid];
}
__global__ void scan2_kernel() {
    __shared__ int sh[SCAN_BLK];
    int tid = threadIdx.x;
    int v = (tid < SCAN_GRID) ? g_bsum[tid] : 0;
    sh[tid] = v;
    __syncthreads();
#pragma unroll
    for (int off = 1; off < SCAN_BLK; off <<= 1) {
        int t = (tid >= off) ? sh[tid - off] : 0;
        __syncthreads();
        sh[tid] += t;
        __syncthreads();
    }
    if (tid < SCAN_GRID) g_bsum[tid] = sh[tid] - v;
    if (tid == 0) g_off[N_NODES] = N_EDGES;
}
__global__ void scan3_kernel() {
    int tid = threadIdx.x;
    int i = blockIdx.x * SCAN_BLK + tid;
    if (i < N_NODES) {
        int o = g_off[i] + g_bsum[blockIdx.x];
        g_off[i] = o;
        g_cur[i] = o;
        g_invdeg[i] = 1.0f / fmaxf((float)g_cnt[i], 1.0f);
    }
}
__global__ void fill_kernel(const int* __restrict__ e_src, const int* __restrict__ e_dst) {
    int e = blockIdx.x * blockDim.x + threadIdx.x;
    if (e < N_EDGES) {
        int d = e_dst[e];
        int pos = atomicAdd(&g_cur[d], 1);
        g_csr[pos] = e_src[e];
    }
}

// ---------------- mean aggregation: fp16 gather, HADD2 accumulate ----------------
// thread handles 8 channels (one uint4 = 4 half2); blockDim.x = F/8
__global__ void aggregate_kernel(int layer) {
    const uint4* feat = (const uint4*)(layer ? g_h1h : g_h0h);
    int Fv8 = (layer ? F1 : F0) >> 3;
    int n = blockIdx.x * blockDim.y + threadIdx.y;
    if (n >= N_NODES) return;
    int c = threadIdx.x;
    int s = g_off[n], e = g_off[n + 1];
    __half2 acc0 = __float2half2_rn(0.f);
    __half2 acc1 = acc0, acc2 = acc0, acc3 = acc0;
    const int* csr = g_csr;
    for (int j = s; j < e; ++j) {
        int srcn = csr[j];
        uint4 v = feat[(size_t)srcn * Fv8 + c];
        const __half2* hv = (const __half2*)&v;
        acc0 = __hadd2(acc0, hv[0]);
        acc1 = __hadd2(acc1, hv[1]);
        acc2 = __hadd2(acc2, hv[2]);
        acc3 = __hadd2(acc3, hv[3]);
    }
    __half2 scale = __float2half2_rn(g_invdeg[n]);
    uint4 outv;
    __half2* ho = (__half2*)&outv;
    ho[0] = __hmul2(acc0, scale);
    ho[1] = __hmul2(acc1, scale);
    ho[2] = __hmul2(acc2, scale);
    ho[3] = __hmul2(acc3, scale);
    ((uint4*)g_aggh)[(size_t)n * Fv8 + c] = outv;
}

// ---------------- tensor-core GEMM: C = relu(agg@Wl + x@Wr + b), fp16 ----------------
struct Pref {
    uint4 a[2], b[2];
};

__device__ __forceinline__ void ldg_chunk(Pref& p, int layer, int F, int nc,
                                          int t, int row0, int col0) {
    int hf = (t >= nc) ? 1 : 0;
    int k0 = (t - hf * nc) * 32;
    const __half* Asrc = hf ? (layer ? g_h1h : g_h0h) : g_aggh;
    const __half* Bsrc = g_wt[layer * 2 + hf];
    int tid = threadIdx.x;
#pragma unroll
    for (int j = 0; j < 2; ++j) {
        int i = tid + j * 256;
        int r = i >> 2, q8 = (i & 3) * 8;
        int gm = row0 + r;
        p.a[j] = (gm < N_NODES) ? *(const uint4*)(Asrc + (size_t)gm * F + k0 + q8)
                                : make_uint4(0, 0, 0, 0);
        p.b[j] = *(const uint4*)(Bsrc + (size_t)(col0 + r) * F + k0 + q8);
    }
}

__device__ __forceinline__ void sts_chunk(const Pref& p, char* stage) {
    int tid = threadIdx.x;
#pragma unroll
    for (int j = 0; j < 2; ++j) {
        int i = tid + j * 256;
        int r = i >> 2, b16 = (i & 3) * 16;
        *(uint4*)(stage + A_H + r * ASTR2 + b16) = p.a[j];
        *(uint4*)(stage + B_H + r * ASTR2 + b16) = p.b[j];
    }
}

__global__ __launch_bounds__(256)
void gemm_mma_kernel(const float* __restrict__ bias, int layer) {
    extern __shared__ char smem[];
    const int F  = layer ? F1 : F0;
    const int nc = F / 32;
    const int T  = 2 * nc;
    const int row0 = blockIdx.x * 128;
    const int col0 = blockIdx.y * 128;
    __half* C = layer ? g_zh : g_h1h;

    const int tid = threadIdx.x, wid = tid >> 5, lane = tid & 31;
    const int wm0 = (wid >> 2) * 64;
    const int wn0 = (wid & 3) * 32;

    float acc[4][4][4];
#pragma unroll
    for (int a = 0; a < 4; ++a)
#pragma unroll
        for (int b = 0; b < 4; ++b)
#pragma unroll
            for (int c = 0; c < 4; ++c) acc[a][b][c] = 0.f;

    Pref p;
    ldg_chunk(p, layer, F, nc, 0, row0, col0);
    sts_chunk(p, smem);
    __syncthreads();

    const uint32_t sbase = smem_u32(smem);
    const int b_row = ((lane >> 4) & 1) * 8 + (lane & 7);
    const int b_khalf = ((lane >> 3) & 1) * 8;
    const int a_row = lane & 15;
    const int a_khalf = ((lane >> 4) & 1) * 8;

    for (int t = 0; t < T; ++t) {
        if (t + 1 < T) ldg_chunk(p, layer, F, nc, t + 1, row0, col0);
        const uint32_t sb = sbase + (uint32_t)(t & 1) * STAGE_BYTES;
#pragma unroll
        for (int ks = 0; ks < 2; ++ks) {
            uint32_t bh[4][2];
            {
                uint32_t r[4];
                uint32_t ad = sb + B_H + (uint32_t)((wn0 + b_row) * ASTR2 + (ks * 16 + b_khalf) * 2);
                ldmx4(r, ad);
                bh[0][0] = r[0]; bh[0][1] = r[1]; bh[1][0] = r[2]; bh[1][1] = r[3];
                ldmx4(r, ad + 16 * ASTR2);
                bh[2][0] = r[0]; bh[2][1] = r[1]; bh[3][0] = r[2]; bh[3][1] = r[3];
            }
            uint32_t ah[4][4];
#pragma unroll
            for (int mt = 0; mt < 4; ++mt) {
                uint32_t roff = (uint32_t)((wm0 + mt * 16 + a_row) * ASTR2 + (ks * 16 + a_khalf) * 2);
                ldmx4(ah[mt], sb + A_H + roff);
            }
#pragma unroll
            for (int mt = 0; mt < 4; ++mt)
#pragma unroll
                for (int nt = 0; nt < 4; ++nt)
                    hmma(acc[mt][nt], ah[mt], bh[nt]);
        }
        if (t + 1 < T) sts_chunk(p, smem + ((t + 1) & 1) * STAGE_BYTES);
        __syncthreads();
    }

    // epilogue: bias + relu + fp16 store
#pragma unroll
    for (int mt = 0; mt < 4; ++mt) {
        int rbase = row0 + wm0 + mt * 16 + (lane >> 2);
#pragma unroll
        for (int hh = 0; hh < 2; ++hh) {
            int gm = rbase + hh * 8;
            if (gm < N_NODES) {
                __half* crow = C + (size_t)gm * HID;
#pragma unroll
                for (int nt = 0; nt < 4; ++nt) {
                    int cn = col0 + wn0 + nt * 8 + (lane & 3) * 2;
                    float v0 = acc[mt][nt][hh * 2]     + bias[cn];
                    float v1 = acc[mt][nt][hh * 2 + 1] + bias[cn + 1];
                    *(__half2*)(crow + cn) = __floats2half2_rn(fmaxf(v0, 0.f), fmaxf(v1, 0.f));
                }
            }
        }
    }
}

// ---------------- pair scoring: sigmoid(dot(z[src], z[dst])), fp16 gather ----------------
__global__ void pair_kernel(const int* __restrict__ src,
                            const int* __restrict__ dst,
                            float* __restrict__ out) {
    int gw = (blockIdx.x * blockDim.x + threadIdx.x) >> 5;
    int lane = threadIdx.x & 31;
    if (gw >= N_PAIRS) return;
    int a = src[gw], b = dst[gw];
    uint4 va = ((const uint4*)(g_zh + (size_t)a * HID))[lane];
    uint4 vb = ((const uint4*)(g_zh + (size_t)b * HID))[lane];
    const __half2* ha = (const __half2*)&va;
    const __half2* hb = (const __half2*)&vb;
    float acc = 0.f;
#pragma unroll
    for (int i = 0; i < 4; ++i) {
        float2 fa = __half22float2(ha[i]);
        float2 fb = __half22float2(hb[i]);
        acc += fa.x * fb.x + fa.y * fb.y;
    }
#pragma unroll
    for (int o = 16; o; o >>= 1) acc += __shfl_xor_sync(0xFFFFFFFFu, acc, o);
    if (lane == 0) out[gw] = 1.f / (1.f + expf(-acc));
}

// ---------------- launch ----------------
extern "C" void kernel_launch(void* const* d_in, const int* in_sizes, int n_in,
                              void* d_out, int out_size) {
    const float* x           = (const float*)d_in[0];
    const int*   tok_ids     = (const int*)  d_in[1];
    const float* scores      = (const float*)d_in[2];
    const int*   cat_ids     = (const int*)  d_in[3];
    const int*   edge_index  = (const int*)  d_in[4];
    const int*   src         = (const int*)  d_in[5];
    const int*   dst         = (const int*)  d_in[6];
    const float* trait_embed = (const float*)d_in[7];
    const float* cat_embed   = (const float*)d_in[8];
    const float* proj_W      = (const float*)d_in[9];
    const float* proj_b      = (const float*)d_in[10];
    const float* W_l0        = (const float*)d_in[11];
    const float* b_l0        = (const float*)d_in[12];
    const float* W_r0        = (const float*)d_in[13];
    const float* W_l1        = (const float*)d_in[14];
    const float* b_l1        = (const float*)d_in[15];
    const float* W_r1        = (const float*)d_in[16];
    float* out = (float*)d_out;

    const int* e_src = edge_index;
    const int* e_dst = edge_index + N_EDGES;

    // static side-stream + events: created once, reused; captured graph is
    // identical on every call (deterministic work).
    static cudaStream_t s2 = nullptr;
    static cudaEvent_t ev_fork = nullptr, ev_join = nullptr;
    if (s2 == nullptr) {
        cudaStreamCreateWithFlags(&s2, cudaStreamNonBlocking);
        cudaEventCreateWithFlags(&ev_fork, cudaEventDisableTiming);
        cudaEventCreateWithFlags(&ev_join, cudaEventDisableTiming);
    }

    cudaFuncSetAttribute(gemm_mma_kernel,
                         cudaFuncAttributeMaxDynamicSharedMemorySize, SMEM_GEMM_TOTAL);

    // fork: CSR chain on s2, feature prep on main stream
    cudaEventRecord(ev_fork, 0);
    cudaStreamWaitEvent(s2, ev_fork, 0);

    zero_cnt_kernel<<<(N_NODES + 255) / 256, 256, 0, s2>>>();
    count_kernel<<<(N_EDGES + 255) / 256, 256, 0, s2>>>(e_dst);
    scan1_kernel<<<SCAN_GRID, SCAN_BLK, 0, s2>>>();
    scan2_kernel<<<1, SCAN_BLK, 0, s2>>>();
    scan3_kernel<<<SCAN_GRID, SCAN_BLK, 0, s2>>>();
    fill_kernel<<<(N_EDGES + 255) / 256, 256, 0, s2>>>(e_src, e_dst);
    cudaEventRecord(ev_join, s2);

    gwas_kernel<<<(N_NODES + 7) / 8, 256>>>(x, tok_ids, scores, cat_ids,
                                            trait_embed, cat_embed, proj_W, proj_b);
    wsplit_all_kernel<<<(256 * 256 + 255) / 256, 256>>>(W_l0, W_r0, W_l1, W_r1);

    // join: aggregation needs both h0 (main) and CSR (s2)
    cudaStreamWaitEvent(0, ev_join, 0);

    const dim3 ggrid((N_NODES + 127) / 128, 2);

    // Layer 0
    {
        dim3 blk(F0 / 8, 12);   // 20 x 12 = 240
        aggregate_kernel<<<(N_NODES + 11) / 12, blk>>>(0);
        gemm_mma_kernel<<<ggrid, 256, SMEM_GEMM_TOTAL>>>(b_l0, 0);
    }
    // Layer 1
    {
        dim3 blk(F1 / 8, 8);    // 32 x 8 = 256
        aggregate_kernel<<<(N_NODES + 7) / 8, blk>>>(1);
        gemm_mma_kernel<<<ggrid, 256, SMEM_GEMM_TOTAL>>>(b_l1, 1);
    }

    pair_kernel<<<(N_PAIRS * 32 + 255) / 256, 256>>>(src, dst, out);
}